// round 4
// baseline (speedup 1.0000x reference)
#include <cuda_runtime.h>
#include <cuda_bf16.h>

#define HIDDEN 1024
#define NHEADS 16
#define HDIM   64
#define BATCH  2
#define SEQ    2048
#define MROWS  (BATCH*SEQ)   // 4096

// Scratch (no cudaMalloc allowed): Q,K,V in [B,H,S,D], ctx in [B,S,HIDDEN]
__device__ float g_Q[MROWS*HIDDEN];
__device__ float g_K[MROWS*HIDDEN];
__device__ float g_V[MROWS*HIDDEN];
__device__ float g_ctx[MROWS*HIDDEN];

// ---------------------------------------------------------------------------
// C = X @ W^T + bias.  X:[M,K] row-major, W:[N,K] row-major, bias:[N].
// MODE 0: out[m*N+n] (plain row-major)
// MODE 1: scatter to [B, H, S, D]:  out[((b*NH+h)*S+s)*D+d]
// BM=BN=128, BK=16, 256 threads, 8x8 per thread. Double-buffered smem:
// one __syncthreads per K-tile; next tile prefetched to registers during
// compute, stored to the alternate buffer.
// ---------------------------------------------------------------------------
template<int MODE>
__global__ __launch_bounds__(256)
void gemm_bias(const float* __restrict__ X, const float* __restrict__ W,
               const float* __restrict__ bias, float* __restrict__ out,
               int M, int N, int K)
{
    constexpr int BM = 128, BN = 128, BK = 16, TM = 8, TN = 8;
    __shared__ float As[2][BK][BM + 4];   // X^T tile: As[buf][k][m]
    __shared__ float Bs[2][BK][BN + 4];   // W^T tile: Bs[buf][k][n]

    const int tid = threadIdx.x;
    const int tx = tid & 15, ty = tid >> 4;
    const int row0 = blockIdx.y * BM, col0 = blockIdx.x * BN;

    // Per-thread load slots (fixed for the whole kernel)
    const int r0a = (tid)      >> 2, c0 = (tid) & 3;
    const int r1a = (tid + 256) >> 2, c1 = (tid + 256) & 3;

    float acc[TM][TN] = {};

    // ---- prologue: load tile k0=0 into buffer 0 ----
    {
        float4 v;
        v = *(const float4*)&X[(size_t)(row0 + r0a) * K + c0 * 4];
        As[0][c0*4+0][r0a] = v.x; As[0][c0*4+1][r0a] = v.y;
        As[0][c0*4+2][r0a] = v.z; As[0][c0*4+3][r0a] = v.w;
        v = *(const float4*)&X[(size_t)(row0 + r1a) * K + c1 * 4];
        As[0][c1*4+0][r1a] = v.x; As[0][c1*4+1][r1a] = v.y;
        As[0][c1*4+2][r1a] = v.z; As[0][c1*4+3][r1a] = v.w;
        v = *(const float4*)&W[(size_t)(col0 + r0a) * K + c0 * 4];
        Bs[0][c0*4+0][r0a] = v.x; Bs[0][c0*4+1][r0a] = v.y;
        Bs[0][c0*4+2][r0a] = v.z; Bs[0][c0*4+3][r0a] = v.w;
        v = *(const float4*)&W[(size_t)(col0 + r1a) * K + c1 * 4];
        Bs[0][c1*4+0][r1a] = v.x; Bs[0][c1*4+1][r1a] = v.y;
        Bs[0][c1*4+2][r1a] = v.z; Bs[0][c1*4+3][r1a] = v.w;
    }
    __syncthreads();

    int buf = 0;
    for (int k0 = BK; k0 < K; k0 += BK) {
        // prefetch next tile gmem -> registers
        float4 ra0 = *(const float4*)&X[(size_t)(row0 + r0a) * K + k0 + c0 * 4];
        float4 ra1 = *(const float4*)&X[(size_t)(row0 + r1a) * K + k0 + c1 * 4];
        float4 rb0 = *(const float4*)&W[(size_t)(col0 + r0a) * K + k0 + c0 * 4];
        float4 rb1 = *(const float4*)&W[(size_t)(col0 + r1a) * K + k0 + c1 * 4];

        // compute on current buffer
        #pragma unroll
        for (int k = 0; k < BK; k++) {
            float a[TM], b[TN];
            #pragma unroll
            for (int i = 0; i < TM; i++) a[i] = As[buf][k][ty * TM + i];
            #pragma unroll
            for (int j = 0; j < TN; j++) b[j] = Bs[buf][k][tx * TN + j];
            #pragma unroll
            for (int i = 0; i < TM; i++)
                #pragma unroll
                for (int j = 0; j < TN; j++)
                    acc[i][j] += a[i] * b[j];
        }

        // store prefetched tile into alternate buffer
        const int nb = buf ^ 1;
        As[nb][c0*4+0][r0a] = ra0.x; As[nb][c0*4+1][r0a] = ra0.y;
        As[nb][c0*4+2][r0a] = ra0.z; As[nb][c0*4+3][r0a] = ra0.w;
        As[nb][c1*4+0][r1a] = ra1.x; As[nb][c1*4+1][r1a] = ra1.y;
        As[nb][c1*4+2][r1a] = ra1.z; As[nb][c1*4+3][r1a] = ra1.w;
        Bs[nb][c0*4+0][r0a] = rb0.x; Bs[nb][c0*4+1][r0a] = rb0.y;
        Bs[nb][c0*4+2][r0a] = rb0.z; Bs[nb][c0*4+3][r0a] = rb0.w;
        Bs[nb][c1*4+0][r1a] = rb1.x; Bs[nb][c1*4+1][r1a] = rb1.y;
        Bs[nb][c1*4+2][r1a] = rb1.z; Bs[nb][c1*4+3][r1a] = rb1.w;
        __syncthreads();
        buf = nb;
    }

    // epilogue compute on last buffer
    #pragma unroll
    for (int k = 0; k < BK; k++) {
        float a[TM], b[TN];
        #pragma unroll
        for (int i = 0; i < TM; i++) a[i] = As[buf][k][ty * TM + i];
        #pragma unroll
        for (int j = 0; j < TN; j++) b[j] = Bs[buf][k][tx * TN + j];
        #pragma unroll
        for (int i = 0; i < TM; i++)
            #pragma unroll
            for (int j = 0; j < TN; j++)
                acc[i][j] += a[i] * b[j];
    }

    #pragma unroll
    for (int i = 0; i < TM; i++) {
        int m = row0 + ty * TM + i;
        #pragma unroll
        for (int j = 0; j < TN; j++) {
            int n = col0 + tx * TN + j;
            float v = acc[i][j] + bias[n];
            if (MODE == 0) {
                out[(size_t)m * N + n] = v;
            } else {
                int b = m / SEQ, s = m % SEQ;
                int h = n / HDIM, d = n % HDIM;
                out[(((size_t)b * NHEADS + h) * SEQ + s) * HDIM + d] = v;
            }
        }
    }
}

// ---------------------------------------------------------------------------
// Flash attention, fp32. One CTA = one (b,h) and 64 queries.
// 256 threads (16x16), 4x4 register tiles for S=QK^T and O+=P V.
// Dynamic smem: Qs[64][65] | KVs (Ks[64][65] then Vs[64][64]) | Ps[64][65]
//               | m[64] | l[64] | alpha[64]  -> 50688 bytes
// ---------------------------------------------------------------------------
__global__ __launch_bounds__(256)
void flash_attn()
{
    extern __shared__ float sm[];
    float* Qs   = sm;            // [64][65], Qs[d*65+q]
    float* KVs  = sm + 4160;     // K phase: [d*65+kv]; V phase: [kv*64+d]
    float* Ps   = sm + 8320;     // [q*65+kv]
    float* mrow = sm + 12480;
    float* lrow = mrow + 64;
    float* arow = lrow + 64;

    const int tid  = threadIdx.x;
    const int tx   = tid & 15, ty = tid >> 4;
    const int lane = tid & 31, warp = tid >> 5;
    const int q0   = blockIdx.x * 64;
    const int bh   = blockIdx.y;

    const float* Qg = g_Q + (size_t)bh * SEQ * HDIM;
    const float* Kg = g_K + (size_t)bh * SEQ * HDIM;
    const float* Vg = g_V + (size_t)bh * SEQ * HDIM;

    // Load Q tile transposed: Qs[d][q]
    #pragma unroll
    for (int i = 0; i < 4; i++) {
        int idx = tid + i * 256;              // 1024 float4 slots
        int r = idx >> 4, d4 = idx & 15;
        float4 v = *(const float4*)&Qg[(size_t)(q0 + r) * HDIM + d4 * 4];
        Qs[(d4*4+0)*65 + r] = v.x; Qs[(d4*4+1)*65 + r] = v.y;
        Qs[(d4*4+2)*65 + r] = v.z; Qs[(d4*4+3)*65 + r] = v.w;
    }
    if (tid < 64) { mrow[tid] = -1e30f; lrow[tid] = 0.f; }

    float acc[4][4] = {};
    __syncthreads();

    for (int kv0 = 0; kv0 < SEQ; kv0 += 64) {
        // Load K tile transposed: Ks[d][kv]
        #pragma unroll
        for (int i = 0; i < 4; i++) {
            int idx = tid + i * 256;
            int r = idx >> 4, d4 = idx & 15;
            float4 v = *(const float4*)&Kg[(size_t)(kv0 + r) * HDIM + d4 * 4];
            KVs[(d4*4+0)*65 + r] = v.x; KVs[(d4*4+1)*65 + r] = v.y;
            KVs[(d4*4+2)*65 + r] = v.z; KVs[(d4*4+3)*65 + r] = v.w;
        }
        __syncthreads();

        // S = Q K^T (4x4 per thread)
        float s[4][4] = {};
        #pragma unroll
        for (int d = 0; d < 64; d++) {
            float a[4], b[4];
            #pragma unroll
            for (int i = 0; i < 4; i++) a[i] = Qs[d*65 + ty*4 + i];
            #pragma unroll
            for (int j = 0; j < 4; j++) b[j] = KVs[d*65 + tx*4 + j];
            #pragma unroll
            for (int i = 0; i < 4; i++)
                #pragma unroll
                for (int j = 0; j < 4; j++)
                    s[i][j] += a[i] * b[j];
        }
        __syncthreads();   // K reads done; KVs can be reused for V

        // Write scaled scores; load V tile (natural layout, stride 64)
        #pragma unroll
        for (int i = 0; i < 4; i++)
            #pragma unroll
            for (int j = 0; j < 4; j++)
                Ps[(ty*4 + i) * 65 + tx*4 + j] = s[i][j] * 0.125f;  // 1/sqrt(64)
        #pragma unroll
        for (int i = 0; i < 4; i++) {
            int idx = tid + i * 256;
            int r = idx >> 4, d4 = idx & 15;
            float4 v = *(const float4*)&Vg[(size_t)(kv0 + r) * HDIM + d4 * 4];
            *(float4*)&KVs[r * 64 + d4 * 4] = v;
        }
        __syncthreads();

        // Online softmax: warp w owns rows [8w, 8w+8)
        #pragma unroll
        for (int rr = 0; rr < 8; rr++) {
            int r = warp * 8 + rr;
            float v0 = Ps[r*65 + lane], v1 = Ps[r*65 + lane + 32];
            float tm = fmaxf(v0, v1);
            #pragma unroll
            for (int off = 16; off; off >>= 1)
                tm = fmaxf(tm, __shfl_xor_sync(0xffffffffu, tm, off));
            float mold = mrow[r];
            float mnew = fmaxf(mold, tm);
            float p0 = __expf(v0 - mnew), p1 = __expf(v1 - mnew);
            Ps[r*65 + lane] = p0; Ps[r*65 + lane + 32] = p1;
            float ps = p0 + p1;
            #pragma unroll
            for (int off = 16; off; off >>= 1)
                ps += __shfl_xor_sync(0xffffffffu, ps, off);
            if (lane == 0) {
                float al = __expf(mold - mnew);
                arow[r] = al;
                lrow[r] = lrow[r] * al + ps;
                mrow[r] = mnew;
            }
        }
        __syncthreads();

        // O = O*alpha + P @ V
        float al[4];
        #pragma unroll
        for (int i = 0; i < 4; i++) al[i] = arow[ty*4 + i];
        #pragma unroll
        for (int i = 0; i < 4; i++)
            #pragma unroll
            for (int j = 0; j < 4; j++)
                acc[i][j] *= al[i];
        #pragma unroll
        for (int kv = 0; kv < 64; kv++) {
            float a[4];
            #pragma unroll
            for (int i = 0; i < 4; i++) a[i] = Ps[(ty*4 + i) * 65 + kv];
            float4 v = *(const float4*)&KVs[kv * 64 + tx * 4];
            #pragma unroll
            for (int i = 0; i < 4; i++) {
                acc[i][0] += a[i] * v.x;
                acc[i][1] += a[i] * v.y;
                acc[i][2] += a[i] * v.z;
                acc[i][3] += a[i] * v.w;
            }
        }
        __syncthreads();   // protect Ps/KVs before next iteration's loads
    }

    // Normalize and write ctx in [B, S, HIDDEN] layout
    const int b = bh / NHEADS, h = bh % NHEADS;
    #pragma unroll
    for (int i = 0; i < 4; i++) {
        int srow = q0 + ty*4 + i;
        float inv = 1.0f / lrow[ty*4 + i];
        float4 o;
        o.x = acc[i][0] * inv; o.y = acc[i][1] * inv;
        o.z = acc[i][2] * inv; o.w = acc[i][3] * inv;
        *(float4*)&g_ctx[((size_t)b * SEQ + srow) * HIDDEN + h * HDIM + tx * 4] = o;
    }
}

// ---------------------------------------------------------------------------
extern "C" void kernel_launch(void* const* d_in, const int* in_sizes, int n_in,
                              void* d_out, int out_size)
{
    const float* query = (const float*)d_in[0];
    const float* key   = (const float*)d_in[1];
    const float* value = (const float*)d_in[2];
    const float* Wq = (const float*)d_in[3];
    const float* bq = (const float*)d_in[4];
    const float* Wk = (const float*)d_in[5];
    const float* bk = (const float*)d_in[6];
    const float* Wv = (const float*)d_in[7];
    const float* bv = (const float*)d_in[8];
    const float* Wo = (const float*)d_in[9];
    const float* bo = (const float*)d_in[10];

    float *gQ, *gK, *gV, *gctx;
    cudaGetSymbolAddress((void**)&gQ,   g_Q);
    cudaGetSymbolAddress((void**)&gK,   g_K);
    cudaGetSymbolAddress((void**)&gV,   g_V);
    cudaGetSymbolAddress((void**)&gctx, g_ctx);

    dim3 ggrid(HIDDEN / 128, MROWS / 128);   // (8, 32)

    gemm_bias<1><<<ggrid, 256>>>(query, Wq, bq, gQ, MROWS, HIDDEN, HIDDEN);
    gemm_bias<1><<<ggrid, 256>>>(key,   Wk, bk, gK, MROWS, HIDDEN, HIDDEN);
    gemm_bias<1><<<ggrid, 256>>>(value, Wv, bv, gV, MROWS, HIDDEN, HIDDEN);

    const size_t smem = 12672 * sizeof(float);  // 50688 B
    cudaFuncSetAttribute(flash_attn, cudaFuncAttributeMaxDynamicSharedMemorySize,
                         (int)smem);
    flash_attn<<<dim3(SEQ / 64, BATCH * NHEADS), 256, smem>>>();

    gemm_bias<0><<<ggrid, 256>>>(gctx, Wo, bo, (float*)d_out, MROWS, HIDDEN, HIDDEN);
}

// round 8
// speedup vs baseline: 1.3275x; 1.3275x over previous
#include <cuda_runtime.h>
#include <cuda_bf16.h>
#include <cstdint>

#define HIDDEN 1024
#define NHEADS 16
#define HDIM   64
#define BATCH  2
#define SEQ    2048
#define MROWS  (BATCH*SEQ)   // 4096

// Scratch: Q,K,V in [B,H,S,D], ctx in [B,S,HIDDEN]
__device__ float g_Q[MROWS*HIDDEN];
__device__ float g_K[MROWS*HIDDEN];
__device__ float g_V[MROWS*HIDDEN];
__device__ float g_ctx[MROWS*HIDDEN];

// ---------------------------------------------------------------------------
// mma.sync m16n8k16 bf16 helper (A row-major, B col-major, fp32 acc)
// ---------------------------------------------------------------------------
__device__ __forceinline__ void mma16816(float* c, const uint32_t* a,
                                         const uint32_t* b)
{
    asm volatile(
        "mma.sync.aligned.m16n8k16.row.col.f32.bf16.bf16.f32 "
        "{%0,%1,%2,%3}, {%4,%5,%6,%7}, {%8,%9}, {%0,%1,%2,%3};"
        : "+f"(c[0]), "+f"(c[1]), "+f"(c[2]), "+f"(c[3])
        : "r"(a[0]), "r"(a[1]), "r"(a[2]), "r"(a[3]), "r"(b[0]), "r"(b[1]));
}

__device__ __forceinline__ uint32_t pack_bf16(__nv_bfloat16 lo, __nv_bfloat16 hi)
{
    __nv_bfloat162 t = __halves2bfloat162(lo, hi);   // .x = halves[0]
    return *(uint32_t*)&t;
}

// ---------------------------------------------------------------------------
// C[4096,1024] = X @ W^T + bias via bf16 hi/lo split (3 MMA passes).
// X:[M,K] row-major, W:[N,K] row-major (W row n == B column n -> row.col mma).
// CTA 128x128, 8 warps (2x4), warp tile 64x32, BK=32.
// MODE 0: row-major out.  MODE 1: scatter to [B,H,S,D].
// ---------------------------------------------------------------------------
template<int MODE>
__global__ __launch_bounds__(256)
void gemm_bf16x2(const float* __restrict__ X, const float* __restrict__ W,
                 const float* __restrict__ bias, float* __restrict__ out)
{
    constexpr int BK = 32, ST = 40;                  // smem stride in halves
    extern __shared__ __nv_bfloat16 smb[];
    __nv_bfloat16* Ah = smb;                         // [128][ST]
    __nv_bfloat16* Al = Ah + 128 * ST;
    __nv_bfloat16* Bh = Al + 128 * ST;
    __nv_bfloat16* Bl = Bh + 128 * ST;

    const int tid  = threadIdx.x;
    const int lane = tid & 31, warp = tid >> 5;
    const int wr = warp >> 2, wc = warp & 3;         // 2 x 4 warp grid
    const int row0 = blockIdx.y * 128, col0 = blockIdx.x * 128;
    const int m0 = wr * 64, n0 = wc * 32;
    const int fr = lane >> 2, fc = lane & 3;         // fragment ids

    float acc[4][4][4] = {};                         // [mi][ni][reg]

    const int gr = tid >> 3, gc4 = tid & 7;          // loader slot

    for (int k0 = 0; k0 < HIDDEN; k0 += BK) {
        // ---- load f32, split into bf16 hi/lo, store to smem ----
        #pragma unroll
        for (int i = 0; i < 4; i++) {
            int r = gr + i * 32;
            float4 v = *(const float4*)&X[(size_t)(row0 + r) * HIDDEN + k0 + gc4 * 4];
            __nv_bfloat16 hx = __float2bfloat16_rn(v.x), hy = __float2bfloat16_rn(v.y);
            __nv_bfloat16 hz = __float2bfloat16_rn(v.z), hw = __float2bfloat16_rn(v.w);
            __nv_bfloat16 lx = __float2bfloat16_rn(v.x - __bfloat162float(hx));
            __nv_bfloat16 ly = __float2bfloat16_rn(v.y - __bfloat162float(hy));
            __nv_bfloat16 lz = __float2bfloat16_rn(v.z - __bfloat162float(hz));
            __nv_bfloat16 lw = __float2bfloat16_rn(v.w - __bfloat162float(hw));
            *(uint32_t*)&Ah[r * ST + gc4 * 4]     = pack_bf16(hx, hy);
            *(uint32_t*)&Ah[r * ST + gc4 * 4 + 2] = pack_bf16(hz, hw);
            *(uint32_t*)&Al[r * ST + gc4 * 4]     = pack_bf16(lx, ly);
            *(uint32_t*)&Al[r * ST + gc4 * 4 + 2] = pack_bf16(lz, lw);

            v = *(const float4*)&W[(size_t)(col0 + r) * HIDDEN + k0 + gc4 * 4];
            hx = __float2bfloat16_rn(v.x); hy = __float2bfloat16_rn(v.y);
            hz = __float2bfloat16_rn(v.z); hw = __float2bfloat16_rn(v.w);
            lx = __float2bfloat16_rn(v.x - __bfloat162float(hx));
            ly = __float2bfloat16_rn(v.y - __bfloat162float(hy));
            lz = __float2bfloat16_rn(v.z - __bfloat162float(hz));
            lw = __float2bfloat16_rn(v.w - __bfloat162float(hw));
            *(uint32_t*)&Bh[r * ST + gc4 * 4]     = pack_bf16(hx, hy);
            *(uint32_t*)&Bh[r * ST + gc4 * 4 + 2] = pack_bf16(hz, hw);
            *(uint32_t*)&Bl[r * ST + gc4 * 4]     = pack_bf16(lx, ly);
            *(uint32_t*)&Bl[r * ST + gc4 * 4 + 2] = pack_bf16(lz, lw);
        }
        __syncthreads();

        // ---- two k=16 steps per chunk ----
        #pragma unroll
        for (int ks = 0; ks < BK; ks += 16) {
            uint32_t ah[4][4], al[4][4], bh[4][2], bl[4][2];
            #pragma unroll
            for (int mi = 0; mi < 4; mi++) {
                const __nv_bfloat16* pa = &Ah[(m0 + mi * 16 + fr) * ST + ks + fc * 2];
                const __nv_bfloat16* pl = &Al[(m0 + mi * 16 + fr) * ST + ks + fc * 2];
                ah[mi][0] = *(const uint32_t*)pa;
                ah[mi][1] = *(const uint32_t*)(pa + 8 * ST);
                ah[mi][2] = *(const uint32_t*)(pa + 8);
                ah[mi][3] = *(const uint32_t*)(pa + 8 * ST + 8);
                al[mi][0] = *(const uint32_t*)pl;
                al[mi][1] = *(const uint32_t*)(pl + 8 * ST);
                al[mi][2] = *(const uint32_t*)(pl + 8);
                al[mi][3] = *(const uint32_t*)(pl + 8 * ST + 8);
            }
            #pragma unroll
            for (int ni = 0; ni < 4; ni++) {
                const __nv_bfloat16* pb = &Bh[(n0 + ni * 8 + fr) * ST + ks + fc * 2];
                const __nv_bfloat16* pl = &Bl[(n0 + ni * 8 + fr) * ST + ks + fc * 2];
                bh[ni][0] = *(const uint32_t*)pb;
                bh[ni][1] = *(const uint32_t*)(pb + 8);
                bl[ni][0] = *(const uint32_t*)pl;
                bl[ni][1] = *(const uint32_t*)(pl + 8);
            }
            #pragma unroll
            for (int mi = 0; mi < 4; mi++)
                #pragma unroll
                for (int ni = 0; ni < 4; ni++) {
                    mma16816(acc[mi][ni], ah[mi], bh[ni]);   // hi*hi
                    mma16816(acc[mi][ni], ah[mi], bl[ni]);   // hi*lo
                    mma16816(acc[mi][ni], al[mi], bh[ni]);   // lo*hi
                }
        }
        __syncthreads();
    }

    // ---- epilogue: add bias, store float2 fragments ----
    #pragma unroll
    for (int mi = 0; mi < 4; mi++) {
        #pragma unroll
        for (int ni = 0; ni < 4; ni++) {
            int gm = row0 + m0 + mi * 16 + fr;
            int gn = col0 + n0 + ni * 8 + fc * 2;
            float b0 = bias[gn], b1 = bias[gn + 1];
            float2 v0 = make_float2(acc[mi][ni][0] + b0, acc[mi][ni][1] + b1);
            float2 v1 = make_float2(acc[mi][ni][2] + b0, acc[mi][ni][3] + b1);
            if (MODE == 0) {
                *(float2*)&out[(size_t)gm * HIDDEN + gn]       = v0;
                *(float2*)&out[(size_t)(gm + 8) * HIDDEN + gn] = v1;
            } else {
                int h = gn >> 6, d = gn & 63;
                int b  = gm >> 11,       s  = gm & 2047;
                int b2 = (gm + 8) >> 11, s2 = (gm + 8) & 2047;
                *(float2*)&out[(((size_t)b  * NHEADS + h) * SEQ + s ) * HDIM + d] = v0;
                *(float2*)&out[(((size_t)b2 * NHEADS + h) * SEQ + s2) * HDIM + d] = v1;
            }
        }
    }
}

// ---------------------------------------------------------------------------
// Flash attention, fp32 (UNCHANGED known-good). One CTA = one (b,h), 64 queries.
// ---------------------------------------------------------------------------
__global__ __launch_bounds__(256)
void flash_attn()
{
    extern __shared__ float sm[];
    float* Qs   = sm;            // [64][65], Qs[d*65+q]
    float* KVs  = sm + 4160;     // K phase: [d*65+kv]; V phase: [kv*64+d]
    float* Ps   = sm + 8320;     // [q*65+kv]
    float* mrow = sm + 12480;
    float* lrow = mrow + 64;
    float* arow = lrow + 64;

    const int tid  = threadIdx.x;
    const int tx   = tid & 15, ty = tid >> 4;
    const int lane = tid & 31, warp = tid >> 5;
    const int q0   = blockIdx.x * 64;
    const int bh   = blockIdx.y;

    const float* Qg = g_Q + (size_t)bh * SEQ * HDIM;
    const float* Kg = g_K + (size_t)bh * SEQ * HDIM;
    const float* Vg = g_V + (size_t)bh * SEQ * HDIM;

    #pragma unroll
    for (int i = 0; i < 4; i++) {
        int idx = tid + i * 256;
        int r = idx >> 4, d4 = idx & 15;
        float4 v = *(const float4*)&Qg[(size_t)(q0 + r) * HDIM + d4 * 4];
        Qs[(d4*4+0)*65 + r] = v.x; Qs[(d4*4+1)*65 + r] = v.y;
        Qs[(d4*4+2)*65 + r] = v.z; Qs[(d4*4+3)*65 + r] = v.w;
    }
    if (tid < 64) { mrow[tid] = -1e30f; lrow[tid] = 0.f; }

    float acc[4][4] = {};
    __syncthreads();

    for (int kv0 = 0; kv0 < SEQ; kv0 += 64) {
        #pragma unroll
        for (int i = 0; i < 4; i++) {
            int idx = tid + i * 256;
            int r = idx >> 4, d4 = idx & 15;
            float4 v = *(const float4*)&Kg[(size_t)(kv0 + r) * HDIM + d4 * 4];
            KVs[(d4*4+0)*65 + r] = v.x; KVs[(d4*4+1)*65 + r] = v.y;
            KVs[(d4*4+2)*65 + r] = v.z; KVs[(d4*4+3)*65 + r] = v.w;
        }
        __syncthreads();

        float s[4][4] = {};
        #pragma unroll
        for (int d = 0; d < 64; d++) {
            float a[4], b[4];
            #pragma unroll
            for (int i = 0; i < 4; i++) a[i] = Qs[d*65 + ty*4 + i];
            #pragma unroll
            for (int j = 0; j < 4; j++) b[j] = KVs[d*65 + tx*4 + j];
            #pragma unroll
            for (int i = 0; i < 4; i++)
                #pragma unroll
                for (int j = 0; j < 4; j++)
                    s[i][j] += a[i] * b[j];
        }
        __syncthreads();

        #pragma unroll
        for (int i = 0; i < 4; i++)
            #pragma unroll
            for (int j = 0; j < 4; j++)
                Ps[(ty*4 + i) * 65 + tx*4 + j] = s[i][j] * 0.125f;
        #pragma unroll
        for (int i = 0; i < 4; i++) {
            int idx = tid + i * 256;
            int r = idx >> 4, d4 = idx & 15;
            float4 v = *(const float4*)&Vg[(size_t)(kv0 + r) * HDIM + d4 * 4];
            *(float4*)&KVs[r * 64 + d4 * 4] = v;
        }
        __syncthreads();

        #pragma unroll
        for (int rr = 0; rr < 8; rr++) {
            int r = warp * 8 + rr;
            float v0 = Ps[r*65 + lane], v1 = Ps[r*65 + lane + 32];
            float tm = fmaxf(v0, v1);
            #pragma unroll
            for (int off = 16; off; off >>= 1)
                tm = fmaxf(tm, __shfl_xor_sync(0xffffffffu, tm, off));
            float mold = mrow[r];
            float mnew = fmaxf(mold, tm);
            float p0 = __expf(v0 - mnew), p1 = __expf(v1 - mnew);
            Ps[r*65 + lane] = p0; Ps[r*65 + lane + 32] = p1;
            float ps = p0 + p1;
            #pragma unroll
            for (int off = 16; off; off >>= 1)
                ps += __shfl_xor_sync(0xffffffffu, ps, off);
            if (lane == 0) {
                float al = __expf(mold - mnew);
                arow[r] = al;
                lrow[r] = lrow[r] * al + ps;
                mrow[r] = mnew;
            }
        }
        __syncthreads();

        float al[4];
        #pragma unroll
        for (int i = 0; i < 4; i++) al[i] = arow[ty*4 + i];
        #pragma unroll
        for (int i = 0; i < 4; i++)
            #pragma unroll
            for (int j = 0; j < 4; j++)
                acc[i][j] *= al[i];
        #pragma unroll
        for (int kv = 0; kv < 64; kv++) {
            float a[4];
            #pragma unroll
            for (int i = 0; i < 4; i++) a[i] = Ps[(ty*4 + i) * 65 + kv];
            float4 v = *(const float4*)&KVs[kv * 64 + tx * 4];
            #pragma unroll
            for (int i = 0; i < 4; i++) {
                acc[i][0] += a[i] * v.x;
                acc[i][1] += a[i] * v.y;
                acc[i][2] += a[i] * v.z;
                acc[i][3] += a[i] * v.w;
            }
        }
        __syncthreads();
    }

    const int b = bh / NHEADS, h = bh % NHEADS;
    #pragma unroll
    for (int i = 0; i < 4; i++) {
        int srow = q0 + ty*4 + i;
        float inv = 1.0f / lrow[ty*4 + i];
        float4 o;
        o.x = acc[i][0] * inv; o.y = acc[i][1] * inv;
        o.z = acc[i][2] * inv; o.w = acc[i][3] * inv;
        *(float4*)&g_ctx[((size_t)b * SEQ + srow) * HIDDEN + h * HDIM + tx * 4] = o;
    }
}

// ---------------------------------------------------------------------------
extern "C" void kernel_launch(void* const* d_in, const int* in_sizes, int n_in,
                              void* d_out, int out_size)
{
    const float* query = (const float*)d_in[0];
    const float* key   = (const float*)d_in[1];
    const float* value = (const float*)d_in[2];
    const float* Wq = (const float*)d_in[3];
    const float* bq = (const float*)d_in[4];
    const float* Wk = (const float*)d_in[5];
    const float* bk = (const float*)d_in[6];
    const float* Wv = (const float*)d_in[7];
    const float* bv = (const float*)d_in[8];
    const float* Wo = (const float*)d_in[9];
    const float* bo = (const float*)d_in[10];

    float *gQ, *gK, *gV, *gctx;
    cudaGetSymbolAddress((void**)&gQ,   g_Q);
    cudaGetSymbolAddress((void**)&gK,   g_K);
    cudaGetSymbolAddress((void**)&gV,   g_V);
    cudaGetSymbolAddress((void**)&gctx, g_ctx);

    dim3 ggrid(HIDDEN / 128, MROWS / 128);   // (8, 32)
    const int gsmem = 4 * 128 * 40 * 2;      // 40960 B

    gemm_bf16x2<1><<<ggrid, 256, gsmem>>>(query, Wq, bq, gQ);
    gemm_bf16x2<1><<<ggrid, 256, gsmem>>>(key,   Wk, bk, gK);
    gemm_bf16x2<1><<<ggrid, 256, gsmem>>>(value, Wv, bv, gV);

    const size_t fsmem = 12672 * sizeof(float);  // 50688 B
    cudaFuncSetAttribute(flash_attn, cudaFuncAttributeMaxDynamicSharedMemorySize,
                         (int)fsmem);
    flash_attn<<<dim3(SEQ / 64, BATCH * NHEADS), 256, fsmem>>>();

    gemm_bf16x2<0><<<ggrid, 256, gsmem>>>(gctx, Wo, bo, (float*)d_out);
}

// round 9
// speedup vs baseline: 2.3039x; 1.7356x over previous
#include <cuda_runtime.h>
#include <cuda_bf16.h>
#include <cstdint>

#define HIDDEN 1024
#define NHEADS 16
#define HDIM   64
#define BATCH  2
#define SEQ    2048
#define MROWS  (BATCH*SEQ)   // 4096

// Scratch: Q,K,V in [B,H,S,D], ctx in [B,S,HIDDEN]
__device__ float g_Q[MROWS*HIDDEN];
__device__ float g_K[MROWS*HIDDEN];
__device__ float g_V[MROWS*HIDDEN];
__device__ float g_ctx[MROWS*HIDDEN];

// ---------------------------------------------------------------------------
// mma.sync m16n8k16 bf16 helper (A row-major, B col-major, fp32 acc)
// ---------------------------------------------------------------------------
__device__ __forceinline__ void mma16816(float* c, const uint32_t* a,
                                         const uint32_t* b)
{
    asm volatile(
        "mma.sync.aligned.m16n8k16.row.col.f32.bf16.bf16.f32 "
        "{%0,%1,%2,%3}, {%4,%5,%6,%7}, {%8,%9}, {%0,%1,%2,%3};"
        : "+f"(c[0]), "+f"(c[1]), "+f"(c[2]), "+f"(c[3])
        : "r"(a[0]), "r"(a[1]), "r"(a[2]), "r"(a[3]), "r"(b[0]), "r"(b[1]));
}

__device__ __forceinline__ uint32_t pack_bf16(__nv_bfloat16 lo, __nv_bfloat16 hi)
{
    __nv_bfloat162 t = __halves2bfloat162(lo, hi);   // .x = halves[0]
    return *(uint32_t*)&t;
}

__device__ __forceinline__ void split2(float x, float y,
                                       uint32_t& hi, uint32_t& lo)
{
    __nv_bfloat16 hx = __float2bfloat16_rn(x), hy = __float2bfloat16_rn(y);
    __nv_bfloat16 lx = __float2bfloat16_rn(x - __bfloat162float(hx));
    __nv_bfloat16 ly = __float2bfloat16_rn(y - __bfloat162float(hy));
    hi = pack_bf16(hx, hy);
    lo = pack_bf16(lx, ly);
}

// ---------------------------------------------------------------------------
// C[4096,1024] = X @ W^T + bias via bf16 hi/lo split (3 MMA passes).
// (unchanged from R8 -- measured good)
// ---------------------------------------------------------------------------
template<int MODE>
__global__ __launch_bounds__(256)
void gemm_bf16x2(const float* __restrict__ X, const float* __restrict__ W,
                 const float* __restrict__ bias, float* __restrict__ out)
{
    constexpr int BK = 32, ST = 40;
    extern __shared__ __nv_bfloat16 smb[];
    __nv_bfloat16* Ah = smb;
    __nv_bfloat16* Al = Ah + 128 * ST;
    __nv_bfloat16* Bh = Al + 128 * ST;
    __nv_bfloat16* Bl = Bh + 128 * ST;

    const int tid  = threadIdx.x;
    const int lane = tid & 31, warp = tid >> 5;
    const int wr = warp >> 2, wc = warp & 3;
    const int row0 = blockIdx.y * 128, col0 = blockIdx.x * 128;
    const int m0 = wr * 64, n0 = wc * 32;
    const int fr = lane >> 2, fc = lane & 3;

    float acc[4][4][4] = {};
    const int gr = tid >> 3, gc4 = tid & 7;

    for (int k0 = 0; k0 < HIDDEN; k0 += BK) {
        #pragma unroll
        for (int i = 0; i < 4; i++) {
            int r = gr + i * 32;
            float4 v = *(const float4*)&X[(size_t)(row0 + r) * HIDDEN + k0 + gc4 * 4];
            uint32_t h0, l0, h1, l1;
            split2(v.x, v.y, h0, l0); split2(v.z, v.w, h1, l1);
            *(uint32_t*)&Ah[r * ST + gc4 * 4]     = h0;
            *(uint32_t*)&Ah[r * ST + gc4 * 4 + 2] = h1;
            *(uint32_t*)&Al[r * ST + gc4 * 4]     = l0;
            *(uint32_t*)&Al[r * ST + gc4 * 4 + 2] = l1;

            v = *(const float4*)&W[(size_t)(col0 + r) * HIDDEN + k0 + gc4 * 4];
            split2(v.x, v.y, h0, l0); split2(v.z, v.w, h1, l1);
            *(uint32_t*)&Bh[r * ST + gc4 * 4]     = h0;
            *(uint32_t*)&Bh[r * ST + gc4 * 4 + 2] = h1;
            *(uint32_t*)&Bl[r * ST + gc4 * 4]     = l0;
            *(uint32_t*)&Bl[r * ST + gc4 * 4 + 2] = l1;
        }
        __syncthreads();

        #pragma unroll
        for (int ks = 0; ks < BK; ks += 16) {
            uint32_t ah[4][4], al[4][4], bh[4][2], bl[4][2];
            #pragma unroll
            for (int mi = 0; mi < 4; mi++) {
                const __nv_bfloat16* pa = &Ah[(m0 + mi * 16 + fr) * ST + ks + fc * 2];
                const __nv_bfloat16* pl = &Al[(m0 + mi * 16 + fr) * ST + ks + fc * 2];
                ah[mi][0] = *(const uint32_t*)pa;
                ah[mi][1] = *(const uint32_t*)(pa + 8 * ST);
                ah[mi][2] = *(const uint32_t*)(pa + 8);
                ah[mi][3] = *(const uint32_t*)(pa + 8 * ST + 8);
                al[mi][0] = *(const uint32_t*)pl;
                al[mi][1] = *(const uint32_t*)(pl + 8 * ST);
                al[mi][2] = *(const uint32_t*)(pl + 8);
                al[mi][3] = *(const uint32_t*)(pl + 8 * ST + 8);
            }
            #pragma unroll
            for (int ni = 0; ni < 4; ni++) {
                const __nv_bfloat16* pb = &Bh[(n0 + ni * 8 + fr) * ST + ks + fc * 2];
                const __nv_bfloat16* pl = &Bl[(n0 + ni * 8 + fr) * ST + ks + fc * 2];
                bh[ni][0] = *(const uint32_t*)pb;
                bh[ni][1] = *(const uint32_t*)(pb + 8);
                bl[ni][0] = *(const uint32_t*)pl;
                bl[ni][1] = *(const uint32_t*)(pl + 8);
            }
            #pragma unroll
            for (int mi = 0; mi < 4; mi++)
                #pragma unroll
                for (int ni = 0; ni < 4; ni++) {
                    mma16816(acc[mi][ni], ah[mi], bh[ni]);
                    mma16816(acc[mi][ni], ah[mi], bl[ni]);
                    mma16816(acc[mi][ni], al[mi], bh[ni]);
                }
        }
        __syncthreads();
    }

    #pragma unroll
    for (int mi = 0; mi < 4; mi++) {
        #pragma unroll
        for (int ni = 0; ni < 4; ni++) {
            int gm = row0 + m0 + mi * 16 + fr;
            int gn = col0 + n0 + ni * 8 + fc * 2;
            float b0 = bias[gn], b1 = bias[gn + 1];
            float2 v0 = make_float2(acc[mi][ni][0] + b0, acc[mi][ni][1] + b1);
            float2 v1 = make_float2(acc[mi][ni][2] + b0, acc[mi][ni][3] + b1);
            if (MODE == 0) {
                *(float2*)&out[(size_t)gm * HIDDEN + gn]       = v0;
                *(float2*)&out[(size_t)(gm + 8) * HIDDEN + gn] = v1;
            } else {
                int h = gn >> 6, d = gn & 63;
                int b  = gm >> 11,       s  = gm & 2047;
                int b2 = (gm + 8) >> 11, s2 = (gm + 8) & 2047;
                *(float2*)&out[(((size_t)b  * NHEADS + h) * SEQ + s ) * HDIM + d] = v0;
                *(float2*)&out[(((size_t)b2 * NHEADS + h) * SEQ + s2) * HDIM + d] = v1;
            }
        }
    }
}

// ---------------------------------------------------------------------------
// Tensor-core flash attention. CTA = 128 queries of one (b,h); 8 warps,
// warp tile M=16 (whole rows -> register-only online softmax).
// KV tile 64. bf16 hi/lo 3-pass mma for both QK^T and PV.
// smem: Khi|Klo [64][72] + Vthi|Vtlo [64][72] = 36864 B
//       (Q staged through same region once at start).
// ---------------------------------------------------------------------------
__global__ __launch_bounds__(256)
void flash_attn_mma()
{
    constexpr int ST = 72;
    extern __shared__ __nv_bfloat16 sm[];
    __nv_bfloat16* Khi  = sm;               // [64][ST]
    __nv_bfloat16* Klo  = sm + 4608;
    __nv_bfloat16* Vthi = sm + 9216;        // transposed: [d][kv]
    __nv_bfloat16* Vtlo = sm + 13824;
    __nv_bfloat16* Qhi  = sm;               // staging: [128][ST]
    __nv_bfloat16* Qlo  = sm + 9216;

    const int tid  = threadIdx.x;
    const int lane = tid & 31, warp = tid >> 5;
    const int fr = lane >> 2, fc = lane & 3;
    const int q0 = blockIdx.x * 128;
    const int bh = blockIdx.y;

    const float* Qg = g_Q + (size_t)bh * SEQ * HDIM;
    const float* Kg = g_K + (size_t)bh * SEQ * HDIM;
    const float* Vg = g_V + (size_t)bh * SEQ * HDIM;

    // ---- stage Q (scaled by 1/8), split hi/lo ----
    #pragma unroll
    for (int i = 0; i < 8; i++) {
        int idx = tid + i * 256;            // 2048 float4 slots
        int r = idx >> 4, c4 = idx & 15;
        float4 v = *(const float4*)&Qg[(size_t)(q0 + r) * HDIM + c4 * 4];
        v.x *= 0.125f; v.y *= 0.125f; v.z *= 0.125f; v.w *= 0.125f;
        uint32_t h0, l0, h1, l1;
        split2(v.x, v.y, h0, l0); split2(v.z, v.w, h1, l1);
        *(uint32_t*)&Qhi[r * ST + c4 * 4]     = h0;
        *(uint32_t*)&Qhi[r * ST + c4 * 4 + 2] = h1;
        *(uint32_t*)&Qlo[r * ST + c4 * 4]     = l0;
        *(uint32_t*)&Qlo[r * ST + c4 * 4 + 2] = l1;
    }
    __syncthreads();

    // ---- extract persistent Q fragments ----
    uint32_t qhi[4][4], qlo[4][4];
    #pragma unroll
    for (int kk = 0; kk < 4; kk++) {
        const __nv_bfloat16* pa = &Qhi[(warp * 16 + fr) * ST + kk * 16 + fc * 2];
        const __nv_bfloat16* pl = &Qlo[(warp * 16 + fr) * ST + kk * 16 + fc * 2];
        qhi[kk][0] = *(const uint32_t*)pa;
        qhi[kk][1] = *(const uint32_t*)(pa + 8 * ST);
        qhi[kk][2] = *(const uint32_t*)(pa + 8);
        qhi[kk][3] = *(const uint32_t*)(pa + 8 * ST + 8);
        qlo[kk][0] = *(const uint32_t*)pl;
        qlo[kk][1] = *(const uint32_t*)(pl + 8 * ST);
        qlo[kk][2] = *(const uint32_t*)(pl + 8);
        qlo[kk][3] = *(const uint32_t*)(pl + 8 * ST + 8);
    }

    float o[8][4] = {};
    float m0r = -1e30f, m1r = -1e30f, l0r = 0.f, l1r = 0.f;

    for (int t = 0; t < SEQ / 64; t++) {
        __syncthreads();                    // smem free (prev readers done)
        // ---- load K (natural) and V (transposed), split hi/lo ----
        #pragma unroll
        for (int i = 0; i < 4; i++) {
            int idx = tid + i * 256;        // 1024 float4 slots
            int r = idx >> 4, c4 = idx & 15;
            float4 v = *(const float4*)&Kg[(size_t)(t * 64 + r) * HDIM + c4 * 4];
            uint32_t h0, l0, h1, l1;
            split2(v.x, v.y, h0, l0); split2(v.z, v.w, h1, l1);
            *(uint32_t*)&Khi[r * ST + c4 * 4]     = h0;
            *(uint32_t*)&Khi[r * ST + c4 * 4 + 2] = h1;
            *(uint32_t*)&Klo[r * ST + c4 * 4]     = l0;
            *(uint32_t*)&Klo[r * ST + c4 * 4 + 2] = l1;

            v = *(const float4*)&Vg[(size_t)(t * 64 + r) * HDIM + c4 * 4];
            float vv[4] = {v.x, v.y, v.z, v.w};
            #pragma unroll
            for (int j = 0; j < 4; j++) {
                __nv_bfloat16 hb = __float2bfloat16_rn(vv[j]);
                __nv_bfloat16 lb = __float2bfloat16_rn(vv[j] - __bfloat162float(hb));
                Vthi[(c4 * 4 + j) * ST + r] = hb;
                Vtlo[(c4 * 4 + j) * ST + r] = lb;
            }
        }
        __syncthreads();

        // ---- S = Q K^T (3 passes) ----
        float s[8][4] = {};
        #pragma unroll
        for (int kk = 0; kk < 4; kk++) {
            #pragma unroll
            for (int ni = 0; ni < 8; ni++) {
                uint32_t bh2[2], bl2[2];
                const __nv_bfloat16* pb = &Khi[(ni * 8 + fr) * ST + kk * 16 + fc * 2];
                const __nv_bfloat16* pl = &Klo[(ni * 8 + fr) * ST + kk * 16 + fc * 2];
                bh2[0] = *(const uint32_t*)pb; bh2[1] = *(const uint32_t*)(pb + 8);
                bl2[0] = *(const uint32_t*)pl; bl2[1] = *(const uint32_t*)(pl + 8);
                mma16816(s[ni], qhi[kk], bh2);
                mma16816(s[ni], qhi[kk], bl2);
                mma16816(s[ni], qlo[kk], bh2);
            }
        }

        // ---- online softmax (registers + quad shfl only) ----
        float tmax0 = -1e30f, tmax1 = -1e30f;
        #pragma unroll
        for (int ni = 0; ni < 8; ni++) {
            tmax0 = fmaxf(tmax0, fmaxf(s[ni][0], s[ni][1]));
            tmax1 = fmaxf(tmax1, fmaxf(s[ni][2], s[ni][3]));
        }
        tmax0 = fmaxf(tmax0, __shfl_xor_sync(0xffffffffu, tmax0, 1));
        tmax0 = fmaxf(tmax0, __shfl_xor_sync(0xffffffffu, tmax0, 2));
        tmax1 = fmaxf(tmax1, __shfl_xor_sync(0xffffffffu, tmax1, 1));
        tmax1 = fmaxf(tmax1, __shfl_xor_sync(0xffffffffu, tmax1, 2));

        float mn0 = fmaxf(m0r, tmax0), mn1 = fmaxf(m1r, tmax1);
        float a0 = __expf(m0r - mn0),  a1 = __expf(m1r - mn1);
        m0r = mn0; m1r = mn1;

        float sum0 = 0.f, sum1 = 0.f;
        uint32_t phi[8][2], plo[8][2];
        #pragma unroll
        for (int ni = 0; ni < 8; ni++) {
            float p00 = __expf(s[ni][0] - mn0), p01 = __expf(s[ni][1] - mn0);
            float p10 = __expf(s[ni][2] - mn1), p11 = __expf(s[ni][3] - mn1);
            sum0 += p00 + p01; sum1 += p10 + p11;
            split2(p00, p01, phi[ni][0], plo[ni][0]);
            split2(p10, p11, phi[ni][1], plo[ni][1]);
        }
        sum0 += __shfl_xor_sync(0xffffffffu, sum0, 1);
        sum0 += __shfl_xor_sync(0xffffffffu, sum0, 2);
        sum1 += __shfl_xor_sync(0xffffffffu, sum1, 1);
        sum1 += __shfl_xor_sync(0xffffffffu, sum1, 2);
        l0r = l0r * a0 + sum0;
        l1r = l1r * a1 + sum1;

        #pragma unroll
        for (int ni = 0; ni < 8; ni++) {
            o[ni][0] *= a0; o[ni][1] *= a0;
            o[ni][2] *= a1; o[ni][3] *= a1;
        }

        // ---- O += P V (3 passes), A-fragments repacked from S fragments ----
        #pragma unroll
        for (int kk = 0; kk < 4; kk++) {
            uint32_t ahz[4] = {phi[2*kk][0], phi[2*kk][1],
                               phi[2*kk+1][0], phi[2*kk+1][1]};
            uint32_t alz[4] = {plo[2*kk][0], plo[2*kk][1],
                               plo[2*kk+1][0], plo[2*kk+1][1]};
            #pragma unroll
            for (int nd = 0; nd < 8; nd++) {
                uint32_t bh2[2], bl2[2];
                const __nv_bfloat16* pb = &Vthi[(nd * 8 + fr) * ST + kk * 16 + fc * 2];
                const __nv_bfloat16* pl = &Vtlo[(nd * 8 + fr) * ST + kk * 16 + fc * 2];
                bh2[0] = *(const uint32_t*)pb; bh2[1] = *(const uint32_t*)(pb + 8);
                bl2[0] = *(const uint32_t*)pl; bl2[1] = *(const uint32_t*)(pl + 8);
                mma16816(o[nd], ahz, bh2);
                mma16816(o[nd], ahz, bl2);
                mma16816(o[nd], alz, bh2);
            }
        }
    }

    // ---- normalize, write ctx [B,S,HIDDEN] ----
    const int b = bh / NHEADS, h = bh % NHEADS;
    const float inv0 = 1.0f / l0r, inv1 = 1.0f / l1r;
    const int q  = q0 + warp * 16 + fr;
    #pragma unroll
    for (int nd = 0; nd < 8; nd++) {
        int d = h * HDIM + nd * 8 + fc * 2;
        float2 v0 = make_float2(o[nd][0] * inv0, o[nd][1] * inv0);
        float2 v1 = make_float2(o[nd][2] * inv1, o[nd][3] * inv1);
        *(float2*)&g_ctx[((size_t)b * SEQ + q    ) * HIDDEN + d] = v0;
        *(float2*)&g_ctx[((size_t)b * SEQ + q + 8) * HIDDEN + d] = v1;
    }
}

// ---------------------------------------------------------------------------
extern "C" void kernel_launch(void* const* d_in, const int* in_sizes, int n_in,
                              void* d_out, int out_size)
{
    const float* query = (const float*)d_in[0];
    const float* key   = (const float*)d_in[1];
    const float* value = (const float*)d_in[2];
    const float* Wq = (const float*)d_in[3];
    const float* bq = (const float*)d_in[4];
    const float* Wk = (const float*)d_in[5];
    const float* bk = (const float*)d_in[6];
    const float* Wv = (const float*)d_in[7];
    const float* bv = (const float*)d_in[8];
    const float* Wo = (const float*)d_in[9];
    const float* bo = (const float*)d_in[10];

    float *gQ, *gK, *gV, *gctx;
    cudaGetSymbolAddress((void**)&gQ,   g_Q);
    cudaGetSymbolAddress((void**)&gK,   g_K);
    cudaGetSymbolAddress((void**)&gV,   g_V);
    cudaGetSymbolAddress((void**)&gctx, g_ctx);

    dim3 ggrid(HIDDEN / 128, MROWS / 128);   // (8, 32)
    const int gsmem = 4 * 128 * 40 * 2;      // 40960 B

    gemm_bf16x2<1><<<ggrid, 256, gsmem>>>(query, Wq, bq, gQ);
    gemm_bf16x2<1><<<ggrid, 256, gsmem>>>(key,   Wk, bk, gK);
    gemm_bf16x2<1><<<ggrid, 256, gsmem>>>(value, Wv, bv, gV);

    const int fsmem = 18432 * 2;             // 36864 B
    flash_attn_mma<<<dim3(SEQ / 128, BATCH * NHEADS), 256, fsmem>>>();

    gemm_bf16x2<0><<<ggrid, 256, gsmem>>>(gctx, Wo, bo, (float*)d_out);
}

// round 12
// speedup vs baseline: 2.5768x; 1.1184x over previous
#include <cuda_runtime.h>
#include <cuda_bf16.h>
#include <cstdint>

#define HIDDEN 1024
#define NHEADS 16
#define HDIM   64
#define BATCH  2
#define SEQ    2048
#define MROWS  (BATCH*SEQ)   // 4096

// Scratch: Q,K,V in [B,H,S,D], ctx in [B,S,HIDDEN]
__device__ float g_Q[MROWS*HIDDEN];
__device__ float g_K[MROWS*HIDDEN];
__device__ float g_V[MROWS*HIDDEN];
__device__ float g_ctx[MROWS*HIDDEN];

// ---------------------------------------------------------------------------
// mma.sync m16n8k16 bf16 helper (A row-major, B col-major, fp32 acc)
// ---------------------------------------------------------------------------
__device__ __forceinline__ void mma16816(float* c, const uint32_t* a,
                                         const uint32_t* b)
{
    asm volatile(
        "mma.sync.aligned.m16n8k16.row.col.f32.bf16.bf16.f32 "
        "{%0,%1,%2,%3}, {%4,%5,%6,%7}, {%8,%9}, {%0,%1,%2,%3};"
        : "+f"(c[0]), "+f"(c[1]), "+f"(c[2]), "+f"(c[3])
        : "r"(a[0]), "r"(a[1]), "r"(a[2]), "r"(a[3]), "r"(b[0]), "r"(b[1]));
}

__device__ __forceinline__ uint32_t pack_bf16(__nv_bfloat16 lo, __nv_bfloat16 hi)
{
    __nv_bfloat162 t = __halves2bfloat162(lo, hi);   // .x = halves[0]
    return *(uint32_t*)&t;
}

__device__ __forceinline__ void split2(float x, float y,
                                       uint32_t& hi, uint32_t& lo)
{
    __nv_bfloat16 hx = __float2bfloat16_rn(x), hy = __float2bfloat16_rn(y);
    __nv_bfloat16 lx = __float2bfloat16_rn(x - __bfloat162float(hx));
    __nv_bfloat16 ly = __float2bfloat16_rn(y - __bfloat162float(hy));
    hi = pack_bf16(hx, hy);
    lo = pack_bf16(lx, ly);
}

// ---------------------------------------------------------------------------
// C[4096,1024] = X @ W^T + bias via bf16 hi/lo split (3 MMA passes).
// (unchanged from R8 -- measured good)
// ---------------------------------------------------------------------------
template<int MODE>
__global__ __launch_bounds__(256)
void gemm_bf16x2(const float* __restrict__ X, const float* __restrict__ W,
                 const float* __restrict__ bias, float* __restrict__ out)
{
    constexpr int BK = 32, ST = 40;
    extern __shared__ __nv_bfloat16 smb[];
    __nv_bfloat16* Ah = smb;
    __nv_bfloat16* Al = Ah + 128 * ST;
    __nv_bfloat16* Bh = Al + 128 * ST;
    __nv_bfloat16* Bl = Bh + 128 * ST;

    const int tid  = threadIdx.x;
    const int lane = tid & 31, warp = tid >> 5;
    const int wr = warp >> 2, wc = warp & 3;
    const int row0 = blockIdx.y * 128, col0 = blockIdx.x * 128;
    const int m0 = wr * 64, n0 = wc * 32;
    const int fr = lane >> 2, fc = lane & 3;

    float acc[4][4][4] = {};
    const int gr = tid >> 3, gc4 = tid & 7;

    for (int k0 = 0; k0 < HIDDEN; k0 += BK) {
        #pragma unroll
        for (int i = 0; i < 4; i++) {
            int r = gr + i * 32;
            float4 v = *(const float4*)&X[(size_t)(row0 + r) * HIDDEN + k0 + gc4 * 4];
            uint32_t h0, l0, h1, l1;
            split2(v.x, v.y, h0, l0); split2(v.z, v.w, h1, l1);
            *(uint32_t*)&Ah[r * ST + gc4 * 4]     = h0;
            *(uint32_t*)&Ah[r * ST + gc4 * 4 + 2] = h1;
            *(uint32_t*)&Al[r * ST + gc4 * 4]     = l0;
            *(uint32_t*)&Al[r * ST + gc4 * 4 + 2] = l1;

            v = *(const float4*)&W[(size_t)(col0 + r) * HIDDEN + k0 + gc4 * 4];
            split2(v.x, v.y, h0, l0); split2(v.z, v.w, h1, l1);
            *(uint32_t*)&Bh[r * ST + gc4 * 4]     = h0;
            *(uint32_t*)&Bh[r * ST + gc4 * 4 + 2] = h1;
            *(uint32_t*)&Bl[r * ST + gc4 * 4]     = l0;
            *(uint32_t*)&Bl[r * ST + gc4 * 4 + 2] = l1;
        }
        __syncthreads();

        #pragma unroll
        for (int ks = 0; ks < BK; ks += 16) {
            uint32_t ah[4][4], al[4][4], bh[4][2], bl[4][2];
            #pragma unroll
            for (int mi = 0; mi < 4; mi++) {
                const __nv_bfloat16* pa = &Ah[(m0 + mi * 16 + fr) * ST + ks + fc * 2];
                const __nv_bfloat16* pl = &Al[(m0 + mi * 16 + fr) * ST + ks + fc * 2];
                ah[mi][0] = *(const uint32_t*)pa;
                ah[mi][1] = *(const uint32_t*)(pa + 8 * ST);
                ah[mi][2] = *(const uint32_t*)(pa + 8);
                ah[mi][3] = *(const uint32_t*)(pa + 8 * ST + 8);
                al[mi][0] = *(const uint32_t*)pl;
                al[mi][1] = *(const uint32_t*)(pl + 8 * ST);
                al[mi][2] = *(const uint32_t*)(pl + 8);
                al[mi][3] = *(const uint32_t*)(pl + 8 * ST + 8);
            }
            #pragma unroll
            for (int ni = 0; ni < 4; ni++) {
                const __nv_bfloat16* pb = &Bh[(n0 + ni * 8 + fr) * ST + ks + fc * 2];
                const __nv_bfloat16* pl = &Bl[(n0 + ni * 8 + fr) * ST + ks + fc * 2];
                bh[ni][0] = *(const uint32_t*)pb;
                bh[ni][1] = *(const uint32_t*)(pb + 8);
                bl[ni][0] = *(const uint32_t*)pl;
                bl[ni][1] = *(const uint32_t*)(pl + 8);
            }
            #pragma unroll
            for (int mi = 0; mi < 4; mi++)
                #pragma unroll
                for (int ni = 0; ni < 4; ni++) {
                    mma16816(acc[mi][ni], ah[mi], bh[ni]);
                    mma16816(acc[mi][ni], ah[mi], bl[ni]);
                    mma16816(acc[mi][ni], al[mi], bh[ni]);
                }
        }
        __syncthreads();
    }

    #pragma unroll
    for (int mi = 0; mi < 4; mi++) {
        #pragma unroll
        for (int ni = 0; ni < 4; ni++) {
            int gm = row0 + m0 + mi * 16 + fr;
            int gn = col0 + n0 + ni * 8 + fc * 2;
            float b0 = bias[gn], b1 = bias[gn + 1];
            float2 v0 = make_float2(acc[mi][ni][0] + b0, acc[mi][ni][1] + b1);
            float2 v1 = make_float2(acc[mi][ni][2] + b0, acc[mi][ni][3] + b1);
            if (MODE == 0) {
                *(float2*)&out[(size_t)gm * HIDDEN + gn]       = v0;
                *(float2*)&out[(size_t)(gm + 8) * HIDDEN + gn] = v1;
            } else {
                int h = gn >> 6, d = gn & 63;
                int b  = gm >> 11,       s  = gm & 2047;
                int b2 = (gm + 8) >> 11, s2 = (gm + 8) & 2047;
                *(float2*)&out[(((size_t)b  * NHEADS + h) * SEQ + s ) * HDIM + d] = v0;
                *(float2*)&out[(((size_t)b2 * NHEADS + h) * SEQ + s2) * HDIM + d] = v1;
            }
        }
    }
}

// ---------------------------------------------------------------------------
// Tensor-core flash attention with double-buffered KV smem.
// CTA = 128 queries of one (b,h); 8 warps, warp tile M=16.
// Per buffer: Khi|Klo [64][72] + Vthi|Vtlo [72-stride transposed] = 36864 B;
// two buffers = 73728 B. One __syncthreads per KV tile; next tile's gmem
// loads are prefetched into registers before compute, converted + stored
// into the alternate buffer after PV.
// ---------------------------------------------------------------------------
__global__ __launch_bounds__(256)
void flash_attn_mma()
{
    constexpr int ST = 72;
    constexpr int BUFW = 4 * 64 * ST;        // halves per buffer (18432)
    extern __shared__ __nv_bfloat16 sm[];

    const int tid  = threadIdx.x;
    const int lane = tid & 31, warp = tid >> 5;
    const int fr = lane >> 2, fc = lane & 3;
    const int q0 = blockIdx.x * 128;
    const int bh = blockIdx.y;

    const float* Qg = g_Q + (size_t)bh * SEQ * HDIM;
    const float* Kg = g_K + (size_t)bh * SEQ * HDIM;
    const float* Vg = g_V + (size_t)bh * SEQ * HDIM;

    // ---- stage Q (scaled 1/8) into buffer-1 space, split hi/lo ----
    {
        __nv_bfloat16* Qhi = sm + BUFW;
        __nv_bfloat16* Qlo = sm + BUFW + 9216;
        #pragma unroll
        for (int i = 0; i < 8; i++) {
            int idx = tid + i * 256;
            int r = idx >> 4, c4 = idx & 15;
            float4 v = *(const float4*)&Qg[(size_t)(q0 + r) * HDIM + c4 * 4];
            v.x *= 0.125f; v.y *= 0.125f; v.z *= 0.125f; v.w *= 0.125f;
            uint32_t h0, l0, h1, l1;
            split2(v.x, v.y, h0, l0); split2(v.z, v.w, h1, l1);
            *(uint32_t*)&Qhi[r * ST + c4 * 4]     = h0;
            *(uint32_t*)&Qhi[r * ST + c4 * 4 + 2] = h1;
            *(uint32_t*)&Qlo[r * ST + c4 * 4]     = l0;
            *(uint32_t*)&Qlo[r * ST + c4 * 4 + 2] = l1;
        }
    }
    __syncthreads();

    // ---- extract persistent Q fragments ----
    uint32_t qhi[4][4], qlo[4][4];
    {
        __nv_bfloat16* Qhi = sm + BUFW;
        __nv_bfloat16* Qlo = sm + BUFW + 9216;
        #pragma unroll
        for (int kk = 0; kk < 4; kk++) {
            const __nv_bfloat16* pa = &Qhi[(warp * 16 + fr) * ST + kk * 16 + fc * 2];
            const __nv_bfloat16* pl = &Qlo[(warp * 16 + fr) * ST + kk * 16 + fc * 2];
            qhi[kk][0] = *(const uint32_t*)pa;
            qhi[kk][1] = *(const uint32_t*)(pa + 8 * ST);
            qhi[kk][2] = *(const uint32_t*)(pa + 8);
            qhi[kk][3] = *(const uint32_t*)(pa + 8 * ST + 8);
            qlo[kk][0] = *(const uint32_t*)pl;
            qlo[kk][1] = *(const uint32_t*)(pl + 8 * ST);
            qlo[kk][2] = *(const uint32_t*)(pl + 8);
            qlo[kk][3] = *(const uint32_t*)(pl + 8 * ST + 8);
        }
    }

    // loader slots
    const int kr  = tid >> 4, kc4 = tid & 15;        // K: row, 4-col group
    const int vrp = tid & 31, vd4g = tid >> 5;       // V: kv-pair, d4 base

    float4 kreg[4], vreg[4];

    // prefetch tile 0
    #pragma unroll
    for (int i = 0; i < 4; i++)
        kreg[i] = *(const float4*)&Kg[(size_t)(kr + i * 16) * HDIM + kc4 * 4];
    #pragma unroll
    for (int u = 0; u < 2; u++) {
        int d4 = vd4g + u * 8;
        vreg[2*u]   = *(const float4*)&Vg[(size_t)(2 * vrp    ) * HDIM + d4 * 4];
        vreg[2*u+1] = *(const float4*)&Vg[(size_t)(2 * vrp + 1) * HDIM + d4 * 4];
    }

    // store tile 0 into buf0
    {
        __nv_bfloat16* Khi  = sm;
        __nv_bfloat16* Klo  = sm + 4608;
        __nv_bfloat16* Vthi = sm + 9216;
        __nv_bfloat16* Vtlo = sm + 13824;
        #pragma unroll
        for (int i = 0; i < 4; i++) {
            int r = kr + i * 16;
            uint32_t h0, l0, h1, l1;
            split2(kreg[i].x, kreg[i].y, h0, l0);
            split2(kreg[i].z, kreg[i].w, h1, l1);
            *(uint32_t*)&Khi[r * ST + kc4 * 4]     = h0;
            *(uint32_t*)&Khi[r * ST + kc4 * 4 + 2] = h1;
            *(uint32_t*)&Klo[r * ST + kc4 * 4]     = l0;
            *(uint32_t*)&Klo[r * ST + kc4 * 4 + 2] = l1;
        }
        #pragma unroll
        for (int u = 0; u < 2; u++) {
            int d4 = vd4g + u * 8;
            float a[4] = {vreg[2*u].x, vreg[2*u].y, vreg[2*u].z, vreg[2*u].w};
            float b[4] = {vreg[2*u+1].x, vreg[2*u+1].y, vreg[2*u+1].z, vreg[2*u+1].w};
            #pragma unroll
            for (int j = 0; j < 4; j++) {
                int d = d4 * 4 + j;
                uint32_t hi, lo;
                split2(a[j], b[j], hi, lo);
                *(uint32_t*)&Vthi[d * ST + 2 * vrp] = hi;
                *(uint32_t*)&Vtlo[d * ST + 2 * vrp] = lo;
            }
        }
    }
    __syncthreads();

    float o[8][4] = {};
    float m0r = -1e30f, m1r = -1e30f, l0r = 0.f, l1r = 0.f;

    for (int t = 0; t < SEQ / 64; t++) {
        __nv_bfloat16* buf = sm + (t & 1) * BUFW;
        __nv_bfloat16* Khi  = buf;
        __nv_bfloat16* Klo  = buf + 4608;
        __nv_bfloat16* Vthi = buf + 9216;
        __nv_bfloat16* Vtlo = buf + 13824;

        // ---- prefetch tile t+1 gmem -> regs (latency hidden under compute) ----
        const bool more = (t + 1 < SEQ / 64);
        if (more) {
            const float* Kt = Kg + (size_t)(t + 1) * 64 * HDIM;
            const float* Vt = Vg + (size_t)(t + 1) * 64 * HDIM;
            #pragma unroll
            for (int i = 0; i < 4; i++)
                kreg[i] = *(const float4*)&Kt[(size_t)(kr + i * 16) * HDIM + kc4 * 4];
            #pragma unroll
            for (int u = 0; u < 2; u++) {
                int d4 = vd4g + u * 8;
                vreg[2*u]   = *(const float4*)&Vt[(size_t)(2 * vrp    ) * HDIM + d4 * 4];
                vreg[2*u+1] = *(const float4*)&Vt[(size_t)(2 * vrp + 1) * HDIM + d4 * 4];
            }
        }

        // ---- S = Q K^T (3 passes) ----
        float s[8][4] = {};
        #pragma unroll
        for (int kk = 0; kk < 4; kk++) {
            #pragma unroll
            for (int ni = 0; ni < 8; ni++) {
                uint32_t bh2[2], bl2[2];
                const __nv_bfloat16* pb = &Khi[(ni * 8 + fr) * ST + kk * 16 + fc * 2];
                const __nv_bfloat16* pl = &Klo[(ni * 8 + fr) * ST + kk * 16 + fc * 2];
                bh2[0] = *(const uint32_t*)pb; bh2[1] = *(const uint32_t*)(pb + 8);
                bl2[0] = *(const uint32_t*)pl; bl2[1] = *(const uint32_t*)(pl + 8);
                mma16816(s[ni], qhi[kk], bh2);
                mma16816(s[ni], qhi[kk], bl2);
                mma16816(s[ni], qlo[kk], bh2);
            }
        }

        // ---- online softmax (registers + quad shfl only) ----
        float tmax0 = -1e30f, tmax1 = -1e30f;
        #pragma unroll
        for (int ni = 0; ni < 8; ni++) {
            tmax0 = fmaxf(tmax0, fmaxf(s[ni][0], s[ni][1]));
            tmax1 = fmaxf(tmax1, fmaxf(s[ni][2], s[ni][3]));
        }
        tmax0 = fmaxf(tmax0, __shfl_xor_sync(0xffffffffu, tmax0, 1));
        tmax0 = fmaxf(tmax0, __shfl_xor_sync(0xffffffffu, tmax0, 2));
        tmax1 = fmaxf(tmax1, __shfl_xor_sync(0xffffffffu, tmax1, 1));
        tmax1 = fmaxf(tmax1, __shfl_xor_sync(0xffffffffu, tmax1, 2));

        float mn0 = fmaxf(m0r, tmax0), mn1 = fmaxf(m1r, tmax1);
        float a0 = __expf(m0r - mn0),  a1 = __expf(m1r - mn1);
        m0r = mn0; m1r = mn1;

        float sum0 = 0.f, sum1 = 0.f;
        uint32_t phi[8][2], plo[8][2];
        #pragma unroll
        for (int ni = 0; ni < 8; ni++) {
            float p00 = __expf(s[ni][0] - mn0), p01 = __expf(s[ni][1] - mn0);
            float p10 = __expf(s[ni][2] - mn1), p11 = __expf(s[ni][3] - mn1);
            sum0 += p00 + p01; sum1 += p10 + p11;
            split2(p00, p01, phi[ni][0], plo[ni][0]);
            split2(p10, p11, phi[ni][1], plo[ni][1]);
        }
        sum0 += __shfl_xor_sync(0xffffffffu, sum0, 1);
        sum0 += __shfl_xor_sync(0xffffffffu, sum0, 2);
        sum1 += __shfl_xor_sync(0xffffffffu, sum1, 1);
        sum1 += __shfl_xor_sync(0xffffffffu, sum1, 2);
        l0r = l0r * a0 + sum0;
        l1r = l1r * a1 + sum1;

        #pragma unroll
        for (int ni = 0; ni < 8; ni++) {
            o[ni][0] *= a0; o[ni][1] *= a0;
            o[ni][2] *= a1; o[ni][3] *= a1;
        }

        // ---- O += P V (3 passes) ----
        #pragma unroll
        for (int kk = 0; kk < 4; kk++) {
            uint32_t ahz[4] = {phi[2*kk][0], phi[2*kk][1],
                               phi[2*kk+1][0], phi[2*kk+1][1]};
            uint32_t alz[4] = {plo[2*kk][0], plo[2*kk][1],
                               plo[2*kk+1][0], plo[2*kk+1][1]};
            #pragma unroll
            for (int nd = 0; nd < 8; nd++) {
                uint32_t bh2[2], bl2[2];
                const __nv_bfloat16* pb = &Vthi[(nd * 8 + fr) * ST + kk * 16 + fc * 2];
                const __nv_bfloat16* pl = &Vtlo[(nd * 8 + fr) * ST + kk * 16 + fc * 2];
                bh2[0] = *(const uint32_t*)pb; bh2[1] = *(const uint32_t*)(pb + 8);
                bl2[0] = *(const uint32_t*)pl; bl2[1] = *(const uint32_t*)(pl + 8);
                mma16816(o[nd], ahz, bh2);
                mma16816(o[nd], ahz, bl2);
                mma16816(o[nd], alz, bh2);
            }
        }

        // ---- convert + store prefetched tile into alternate buffer ----
        if (more) {
            __nv_bfloat16* nbuf = sm + ((t + 1) & 1) * BUFW;
            __nv_bfloat16* nKhi  = nbuf;
            __nv_bfloat16* nKlo  = nbuf + 4608;
            __nv_bfloat16* nVthi = nbuf + 9216;
            __nv_bfloat16* nVtlo = nbuf + 13824;
            #pragma unroll
            for (int i = 0; i < 4; i++) {
                int r = kr + i * 16;
                uint32_t h0, l0, h1, l1;
                split2(kreg[i].x, kreg[i].y, h0, l0);
                split2(kreg[i].z, kreg[i].w, h1, l1);
                *(uint32_t*)&nKhi[r * ST + kc4 * 4]     = h0;
                *(uint32_t*)&nKhi[r * ST + kc4 * 4 + 2] = h1;
                *(uint32_t*)&nKlo[r * ST + kc4 * 4]     = l0;
                *(uint32_t*)&nKlo[r * ST + kc4 * 4 + 2] = l1;
            }
            #pragma unroll
            for (int u = 0; u < 2; u++) {
                int d4 = vd4g + u * 8;
                float a[4] = {vreg[2*u].x, vreg[2*u].y, vreg[2*u].z, vreg[2*u].w};
                float b[4] = {vreg[2*u+1].x, vreg[2*u+1].y, vreg[2*u+1].z, vreg[2*u+1].w};
                #pragma unroll
                for (int j = 0; j < 4; j++) {
                    int d = d4 * 4 + j;
                    uint32_t hi, lo;
                    split2(a[j], b[j], hi, lo);
                    *(uint32_t*)&nVthi[d * ST + 2 * vrp] = hi;
                    *(uint32_t*)&nVtlo[d * ST + 2 * vrp] = lo;
                }
            }
        }
        __syncthreads();
    }

    // ---- normalize, write ctx [B,S,HIDDEN] ----
    const int b = bh / NHEADS, h = bh % NHEADS;
    const float inv0 = 1.0f / l0r, inv1 = 1.0f / l1r;
    const int q  = q0 + warp * 16 + fr;
    #pragma unroll
    for (int nd = 0; nd < 8; nd++) {
        int d = h * HDIM + nd * 8 + fc * 2;
        float2 v0 = make_float2(o[nd][0] * inv0, o[nd][1] * inv0);
        float2 v1 = make_float2(o[nd][2] * inv1, o[nd][3] * inv1);
        *(float2*)&g_ctx[((size_t)b * SEQ + q    ) * HIDDEN + d] = v0;
        *(float2*)&g_ctx[((size_t)b * SEQ + q + 8) * HIDDEN + d] = v1;
    }
}

// ---------------------------------------------------------------------------
extern "C" void kernel_launch(void* const* d_in, const int* in_sizes, int n_in,
                              void* d_out, int out_size)
{
    const float* query = (const float*)d_in[0];
    const float* key   = (const float*)d_in[1];
    const float* value = (const float*)d_in[2];
    const float* Wq = (const float*)d_in[3];
    const float* bq = (const float*)d_in[4];
    const float* Wk = (const float*)d_in[5];
    const float* bk = (const float*)d_in[6];
    const float* Wv = (const float*)d_in[7];
    const float* bv = (const float*)d_in[8];
    const float* Wo = (const float*)d_in[9];
    const float* bo = (const float*)d_in[10];

    float *gQ, *gK, *gV, *gctx;
    cudaGetSymbolAddress((void**)&gQ,   g_Q);
    cudaGetSymbolAddress((void**)&gK,   g_K);
    cudaGetSymbolAddress((void**)&gV,   g_V);
    cudaGetSymbolAddress((void**)&gctx, g_ctx);

    dim3 ggrid(HIDDEN / 128, MROWS / 128);   // (8, 32)
    const int gsmem = 4 * 128 * 40 * 2;      // 40960 B

    gemm_bf16x2<1><<<ggrid, 256, gsmem>>>(query, Wq, bq, gQ);
    gemm_bf16x2<1><<<ggrid, 256, gsmem>>>(key,   Wk, bk, gK);
    gemm_bf16x2<1><<<ggrid, 256, gsmem>>>(value, Wv, bv, gV);

    const int fsmem = 2 * 18432 * 2;         // 73728 B
    cudaFuncSetAttribute(flash_attn_mma,
                         cudaFuncAttributeMaxDynamicSharedMemorySize, fsmem);
    flash_attn_mma<<<dim3(SEQ / 128, BATCH * NHEADS), 256, fsmem>>>();

    gemm_bf16x2<0><<<ggrid, 256, gsmem>>>(gctx, Wo, bo, (float*)d_out);
}